// round 3
// baseline (speedup 1.0000x reference)
#include <cuda_runtime.h>
#include <math.h>

#define TT    512
#define DPOI  256
#define DIN   260
#define DHID  356
#define G3    1536
#define HH    512
#define NC3   64          // CTAs in GRU kernel
#define DPC   8           // h-dims per CTA
#define RPC   24          // rows per CTA (3 gates * 8)

__device__ float g_x   [TT * DPOI];
__device__ float g_gi  [TT * G3];
__device__ float g_hs  [TT * HH];
__device__ float g_hcomm[2 * HH];
__device__ int   g_flags[NC3];

__device__ __forceinline__ float warp_sum(float v) {
#pragma unroll
    for (int o = 16; o > 0; o >>= 1) v += __shfl_xor_sync(0xffffffffu, v, o);
    return v;
}
__device__ __forceinline__ int ld_acq(const int* p) {
    int v; asm volatile("ld.global.acquire.gpu.b32 %0, [%1];" : "=r"(v) : "l"(p) : "memory");
    return v;
}
__device__ __forceinline__ void st_rel(int* p, int v) {
    asm volatile("st.global.release.gpu.b32 [%0], %1;" :: "l"(p), "r"(v) : "memory");
}

// ---------------------------------------------------------------- reset
__global__ void k0_reset() {
    if (threadIdx.x < NC3) g_flags[threadIdx.x] = 0;
}

// ---------------------------------------------------------------- K1: gather+feat+LN+MLP
__global__ __launch_bounds__(256) void k1_feat_mlp(
    const int* __restrict__ idx, const float* __restrict__ tf,
    const float* __restrict__ emb, const float* __restrict__ ll,
    const float* __restrict__ lnw, const float* __restrict__ lnb,
    const float* __restrict__ w1, const float* __restrict__ b1,
    const float* __restrict__ w2, const float* __restrict__ b2)
{
    __shared__ float xs[8 * DIN];
    __shared__ float hb[8 * DHID];
    const int tid = threadIdx.x, warp = tid >> 5, lane = tid & 31;
    const int t0 = blockIdx.x * 8;

    {   // one warp per timestep: gather + features + LayerNorm
        const int t = t0 + warp;
        const int pid = idx[t];
        const float4* er = (const float4*)(emb + (size_t)pid * DPOI);
        *(float4*)(xs + warp * DIN + 4 * lane)       = er[lane];
        *(float4*)(xs + warp * DIN + 128 + 4 * lane) = er[lane + 32];
        if (lane == 0) {
            float tc = fminf(fmaxf(tf[t], 0.f), 1.f);
            float s, c; sincosf(6.283185307179586f * tc, &s, &c);
            float f2 = 0.f, f3 = 0.f;
            if (t > 0) {
                float tp = fminf(fmaxf(tf[t - 1], 0.f), 1.f);
                float d = tc - tp;
                float m = d - floorf(d);
                f2 = log1pf(m * 24.f);
                const int ia = idx[t - 1];
                const float R = 0.017453292519943295f;
                float la1 = R * fminf(fmaxf(ll[2 * ia  + 0],  -90.f),  90.f);
                float lo1 = R * fminf(fmaxf(ll[2 * ia  + 1], -180.f), 180.f);
                float la2 = R * fminf(fmaxf(ll[2 * pid + 0],  -90.f),  90.f);
                float lo2 = R * fminf(fmaxf(ll[2 * pid + 1], -180.f), 180.f);
                float sa = sinf((la2 - la1) * 0.5f);
                float sb = sinf((lo2 - lo1) * 0.5f);
                float a = sa * sa + cosf(la1) * cosf(la2) * sb * sb;
                a = fminf(fmaxf(a, 0.f), 1.f);
                float cc = 2.f * atan2f(sqrtf(a), sqrtf(fmaxf(1.f - a, 1e-12f)));
                f3 = log1pf(6371.0088f * cc);
            }
            xs[warp * DIN + 256] = s;  xs[warp * DIN + 257] = c;
            xs[warp * DIN + 258] = f2; xs[warp * DIN + 259] = f3;
        }
        __syncwarp();
        float sm = 0.f, s2 = 0.f;
        for (int k = lane; k < DIN; k += 32) { float v = xs[warp * DIN + k]; sm += v; s2 += v * v; }
        sm = warp_sum(sm); s2 = warp_sum(s2);
        const float mu = sm * (1.f / DIN);
        const float inv = rsqrtf(s2 * (1.f / DIN) - mu * mu + 1e-5f);
        for (int k = lane; k < DIN; k += 32) {
            float v = xs[warp * DIN + k];
            xs[warp * DIN + k] = (v - mu) * inv * __ldg(&lnw[k]) + __ldg(&lnb[k]);
        }
    }
    __syncthreads();

    // hidden = GELU(x @ W1 + b1); thread owns h0=tid and h1=tid+256
    float acc0[8], acc1[8];
#pragma unroll
    for (int i = 0; i < 8; i++) { acc0[i] = 0.f; acc1[i] = 0.f; }
    const int h0 = tid, h1 = tid + 256;
    const bool h1v = (h1 < DHID);
    for (int k4 = 0; k4 < DIN / 4; k4++) {
        float4 xv[8];
#pragma unroll
        for (int i = 0; i < 8; i++) xv[i] = *(const float4*)(xs + i * DIN + 4 * k4);
#pragma unroll
        for (int c = 0; c < 4; c++) {
            const int k = 4 * k4 + c;
            const float wa = __ldg(&w1[k * DHID + h0]);
            const float wb = h1v ? __ldg(&w1[k * DHID + h1]) : 0.f;
#pragma unroll
            for (int i = 0; i < 8; i++) {
                float xk = (c == 0) ? xv[i].x : (c == 1) ? xv[i].y : (c == 2) ? xv[i].z : xv[i].w;
                acc0[i] = fmaf(xk, wa, acc0[i]);
                acc1[i] = fmaf(xk, wb, acc1[i]);
            }
        }
    }
    {
        const float bb0 = __ldg(&b1[h0]);
        const float bb1 = h1v ? __ldg(&b1[h1]) : 0.f;
#pragma unroll
        for (int i = 0; i < 8; i++) {
            float v = acc0[i] + bb0;
            hb[i * DHID + h0] = 0.5f * v * (1.f + erff(v * 0.7071067811865475f));
            if (h1v) {
                float u = acc1[i] + bb1;
                hb[i * DHID + h1] = 0.5f * u * (1.f + erff(u * 0.7071067811865475f));
            }
        }
    }
    __syncthreads();

    // out = hidden @ W2 + b2; thread owns o=tid
    float acc[8];
#pragma unroll
    for (int i = 0; i < 8; i++) acc[i] = 0.f;
    for (int k4 = 0; k4 < DHID / 4; k4++) {
        float4 hv[8];
#pragma unroll
        for (int i = 0; i < 8; i++) hv[i] = *(const float4*)(hb + i * DHID + 4 * k4);
#pragma unroll
        for (int c = 0; c < 4; c++) {
            const int k = 4 * k4 + c;
            const float w = __ldg(&w2[k * DPOI + tid]);
#pragma unroll
            for (int i = 0; i < 8; i++) {
                float xk = (c == 0) ? hv[i].x : (c == 1) ? hv[i].y : (c == 2) ? hv[i].z : hv[i].w;
                acc[i] = fmaf(xk, w, acc[i]);
            }
        }
    }
    const float bo = __ldg(&b2[tid]);
#pragma unroll
    for (int i = 0; i < 8; i++) g_x[(t0 + i) * DPOI + tid] = acc[i] + bo;
}

// ---------------------------------------------------------------- K2: gi = x @ W_ih^T + b_ih
__global__ __launch_bounds__(256) void k2_gi(
    const float* __restrict__ wih, const float* __restrict__ bih)
{
    __shared__ float xsm[8 * DPOI];
    __shared__ float wsmT[16 * 257];
    const int tid = threadIdx.x;
    const int t0 = blockIdx.x * 8;
    const int g0 = blockIdx.y * 256;

    for (int i = tid; i < 8 * DPOI; i += 256) xsm[i] = g_x[t0 * DPOI + i];

    float acc[8];
#pragma unroll
    for (int i = 0; i < 8; i++) acc[i] = 0.f;

    for (int k0 = 0; k0 < DPOI; k0 += 16) {
        __syncthreads();
        for (int i = tid; i < 4096; i += 256) {
            const int kk = i & 15, g = i >> 4;
            wsmT[kk * 257 + g] = wih[(size_t)(g0 + g) * DPOI + k0 + kk];
        }
        __syncthreads();
#pragma unroll
        for (int k4 = 0; k4 < 4; k4++) {
            float4 xv[8];
#pragma unroll
            for (int i = 0; i < 8; i++) xv[i] = *(const float4*)(xsm + i * DPOI + k0 + 4 * k4);
#pragma unroll
            for (int c = 0; c < 4; c++) {
                const float w = wsmT[(4 * k4 + c) * 257 + tid];
#pragma unroll
                for (int i = 0; i < 8; i++) {
                    float xk = (c == 0) ? xv[i].x : (c == 1) ? xv[i].y : (c == 2) ? xv[i].z : xv[i].w;
                    acc[i] = fmaf(xk, w, acc[i]);
                }
            }
        }
    }
    const float b = __ldg(&bih[g0 + tid]);
#pragma unroll
    for (int i = 0; i < 8; i++) g_gi[(size_t)(t0 + i) * G3 + g0 + tid] = acc[i] + b;
}

// ---------------------------------------------------------------- K3: GRU scan (64 persistent CTAs)
__global__ void __launch_bounds__(256, 1) k3_gru(
    const float* __restrict__ whh, const float* __restrict__ bhh)
{
    extern __shared__ float sm[];
    float* ws   = sm;                 // 24*512 weights
    float* hcur = ws + RPC * HH;      // 512
    float* ghs  = hcur + HH;          // 24
    float* gis  = ghs + RPC;          // 24
    float* bsh  = gis + RPC;          // 24

    const int tid = threadIdx.x, warp = tid >> 5, lane = tid & 31;
    const int c = blockIdx.x;

    // resident weight slice: row m -> global row (m/8)*512 + c*8 + (m%8)
    for (int i = tid; i < RPC * HH; i += 256) {
        const int m = i >> 9, k = i & 511;
        const int grow = (m >> 3) * HH + c * DPC + (m & 7);
        ws[i] = whh[(size_t)grow * HH + k];
    }
    int myrow = -1;
    if (tid < RPC) {
        myrow = (tid >> 3) * HH + c * DPC + (tid & 7);
        bsh[tid] = bhh[myrow];
    }
    for (int i = tid; i < HH; i += 256) hcur[i] = 0.f;
    __syncthreads();

    const float* w0 = ws + (3 * warp + 0) * HH;
    const float* w1 = ws + (3 * warp + 1) * HH;
    const float* w2 = ws + (3 * warp + 2) * HH;

    for (int t = 0; t < TT; t++) {
        float gval = 0.f;
        if (tid < RPC) gval = __ldcg(&g_gi[(size_t)t * G3 + myrow]);

        // 24 dot products: 3 rows per warp
        float a0 = 0.f, a1 = 0.f, a2 = 0.f;
#pragma unroll
        for (int i = 0; i < 16; i++) {
            const float h = hcur[lane + 32 * i];
            a0 = fmaf(w0[lane + 32 * i], h, a0);
            a1 = fmaf(w1[lane + 32 * i], h, a1);
            a2 = fmaf(w2[lane + 32 * i], h, a2);
        }
        a0 = warp_sum(a0); a1 = warp_sum(a1); a2 = warp_sum(a2);
        if (lane == 0) { ghs[3 * warp] = a0; ghs[3 * warp + 1] = a1; ghs[3 * warp + 2] = a2; }
        if (tid < RPC) gis[tid] = gval;
        __syncthreads();

        if (tid < DPC) {
            const int m = tid;
            const float r = 1.f / (1.f + expf(-(gis[m] + ghs[m] + bsh[m])));
            const float z = 1.f / (1.f + expf(-(gis[8 + m] + ghs[8 + m] + bsh[8 + m])));
            const float n = tanhf(gis[16 + m] + r * (ghs[16 + m] + bsh[16 + m]));
            const float hn = (1.f - z) * n + z * hcur[c * DPC + m];
            g_hcomm[(t & 1) * HH + c * DPC + m] = hn;
            g_hs[(size_t)t * HH + c * DPC + m] = hn;
        }
        __threadfence();
        __syncthreads();
        if (tid == 0) st_rel(&g_flags[c], t + 1);
        if (tid < 32) {
            const int tgt = t + 1;
            while (ld_acq(&g_flags[tid]) < tgt || ld_acq(&g_flags[tid + 32]) < tgt) { }
        }
        __syncthreads();
        for (int i = tid; i < HH; i += 256) hcur[i] = __ldcg(&g_hcomm[(t & 1) * HH + i]);
        __syncthreads();
    }
}

// ---------------------------------------------------------------- K4: score + softmax + summary
__global__ __launch_bounds__(512) void k4_epi(
    const float* __restrict__ q, const float* __restrict__ loglam,
    float* __restrict__ out, int out_size)
{
    __shared__ float qs[HH];
    __shared__ float sc[TT];
    __shared__ float red[16];
    const int tid = threadIdx.x, warp = tid >> 5, lane = tid & 31;
    const float lam = fmaxf(expf(loglam[0]), 1e-4f);

    qs[tid] = q[tid] * rsqrtf((float)HH);
    __syncthreads();

    // scores: warp w handles rows [32w, 32w+32)
    for (int rr = 0; rr < 32; rr++) {
        const int t = warp * 32 + rr;
        float a = 0.f;
#pragma unroll
        for (int i = 0; i < 16; i++)
            a = fmaf(g_hs[(size_t)t * HH + lane + 32 * i], qs[lane + 32 * i], a);
        a = warp_sum(a);
        if (lane == 0) sc[t] = a - lam * (float)(TT - 1 - t);
    }
    __syncthreads();

    // softmax over 512
    float v = sc[tid];
    float m = v;
#pragma unroll
    for (int o = 16; o > 0; o >>= 1) m = fmaxf(m, __shfl_xor_sync(0xffffffffu, m, o));
    if (lane == 0) red[warp] = m;
    __syncthreads();
    if (tid < 16) {
        float x = red[tid];
#pragma unroll
        for (int o = 8; o > 0; o >>= 1) x = fmaxf(x, __shfl_xor_sync(0xffffu, x, o));
        if (tid == 0) red[0] = x;
    }
    __syncthreads();
    const float mx = red[0];
    float e = expf(v - mx);
    float s = warp_sum(e);
    __syncthreads();
    if (lane == 0) red[warp] = s;
    __syncthreads();
    if (tid < 16) {
        float x = red[tid];
#pragma unroll
        for (int o = 8; o > 0; o >>= 1) x += __shfl_xor_sync(0xffffu, x, o);
        if (tid == 0) red[0] = x;
    }
    __syncthreads();
    const float attn = e / red[0];
    sc[tid] = attn;                    // reuse sc for attn
    if (out_size >= 1024) out[HH + tid] = attn;
    __syncthreads();

    // summary[j] = sum_t attn[t] * hs[t][j]
    float acc = 0.f;
    for (int t = 0; t < TT; t += 4) {
        acc = fmaf(sc[t],     g_hs[(size_t)t       * HH + tid], acc);
        acc = fmaf(sc[t + 1], g_hs[(size_t)(t + 1) * HH + tid], acc);
        acc = fmaf(sc[t + 2], g_hs[(size_t)(t + 2) * HH + tid], acc);
        acc = fmaf(sc[t + 3], g_hs[(size_t)(t + 3) * HH + tid], acc);
    }
    if (tid < out_size) out[tid] = acc;
}

// ---------------------------------------------------------------- launch
extern "C" void kernel_launch(void* const* d_in, const int* in_sizes, int n_in,
                              void* d_out, int out_size) {
    const int*   idx = (const int*)  d_in[0];
    const float* tf  = (const float*)d_in[1];
    const float* emb = (const float*)d_in[2];
    const float* ll  = (const float*)d_in[3];
    const float* lnw = (const float*)d_in[4];
    const float* lnb = (const float*)d_in[5];
    const float* w1  = (const float*)d_in[6];
    const float* b1  = (const float*)d_in[7];
    const float* w2  = (const float*)d_in[8];
    const float* b2  = (const float*)d_in[9];
    const float* wih = (const float*)d_in[10];
    const float* whh = (const float*)d_in[11];
    const float* bih = (const float*)d_in[12];
    const float* bhh = (const float*)d_in[13];
    const float* q   = (const float*)d_in[14];
    const float* llm = (const float*)d_in[15];
    float* out = (float*)d_out;

    const int k3_smem = (RPC * HH + HH + 3 * RPC) * (int)sizeof(float);
    cudaFuncSetAttribute(k3_gru, cudaFuncAttributeMaxDynamicSharedMemorySize, k3_smem);

    k0_reset<<<1, 64>>>();
    k1_feat_mlp<<<64, 256>>>(idx, tf, emb, ll, lnw, lnb, w1, b1, w2, b2);
    k2_gi<<<dim3(64, 6), 256>>>(wih, bih);
    k3_gru<<<NC3, 256, k3_smem>>>(whh, bhh);
    k4_epi<<<1, 512>>>(q, llm, out, out_size);
}

// round 4
// speedup vs baseline: 2.8100x; 2.8100x over previous
#include <cuda_runtime.h>
#include <math.h>

#define TT    512
#define DPOI  256
#define DIN   260
#define DHID  356
#define G3    1536
#define HH    512
#define CL    16          // cluster size (CTAs in GRU kernel)
#define DPC   32          // h-dims per CTA
#define RPC   96          // rows per CTA (3 gates * 32)
#define RPW   6           // rows per warp (16 warps * 6 = 96)

__device__ float g_x [TT * DPOI];
__device__ float g_gi[TT * G3];
__device__ float g_hs[TT * HH];

__device__ __forceinline__ float warp_sum(float v) {
#pragma unroll
    for (int o = 16; o > 0; o >>= 1) v += __shfl_xor_sync(0xffffffffu, v, o);
    return v;
}
__device__ __forceinline__ unsigned smem_u32(const void* p) {
    unsigned a;
    asm("{ .reg .u64 t; cvta.to.shared.u64 t, %1; cvt.u32.u64 %0, t; }" : "=r"(a) : "l"(p));
    return a;
}
__device__ __forceinline__ void st_dsmem(unsigned addr, unsigned rank, float v) {
    unsigned ra;
    asm volatile("mapa.shared::cluster.u32 %0, %1, %2;" : "=r"(ra) : "r"(addr), "r"(rank));
    asm volatile("st.shared::cluster.f32 [%0], %1;" :: "r"(ra), "f"(v) : "memory");
}
__device__ __forceinline__ void cluster_sync_() {
    asm volatile("barrier.cluster.arrive.aligned;" ::: "memory");
    asm volatile("barrier.cluster.wait.aligned;"   ::: "memory");
}

// ---------------------------------------------------------------- K1: gather+feat+LN+MLP
__global__ __launch_bounds__(256) void k1_feat_mlp(
    const int* __restrict__ idx, const float* __restrict__ tf,
    const float* __restrict__ emb, const float* __restrict__ ll,
    const float* __restrict__ lnw, const float* __restrict__ lnb,
    const float* __restrict__ w1, const float* __restrict__ b1,
    const float* __restrict__ w2, const float* __restrict__ b2)
{
    __shared__ float xs[8 * DIN];
    __shared__ float hb[8 * DHID];
    const int tid = threadIdx.x, warp = tid >> 5, lane = tid & 31;
    const int t0 = blockIdx.x * 8;

    {   // one warp per timestep: gather + features + LayerNorm
        const int t = t0 + warp;
        const int pid = idx[t];
        const float4* er = (const float4*)(emb + (size_t)pid * DPOI);
        *(float4*)(xs + warp * DIN + 4 * lane)       = er[lane];
        *(float4*)(xs + warp * DIN + 128 + 4 * lane) = er[lane + 32];
        if (lane == 0) {
            float tc = fminf(fmaxf(tf[t], 0.f), 1.f);
            float s, c; sincosf(6.283185307179586f * tc, &s, &c);
            float f2 = 0.f, f3 = 0.f;
            if (t > 0) {
                float tp = fminf(fmaxf(tf[t - 1], 0.f), 1.f);
                float d = tc - tp;
                float m = d - floorf(d);
                f2 = log1pf(m * 24.f);
                const int ia = idx[t - 1];
                const float R = 0.017453292519943295f;
                float la1 = R * fminf(fmaxf(ll[2 * ia  + 0],  -90.f),  90.f);
                float lo1 = R * fminf(fmaxf(ll[2 * ia  + 1], -180.f), 180.f);
                float la2 = R * fminf(fmaxf(ll[2 * pid + 0],  -90.f),  90.f);
                float lo2 = R * fminf(fmaxf(ll[2 * pid + 1], -180.f), 180.f);
                float sa = sinf((la2 - la1) * 0.5f);
                float sb = sinf((lo2 - lo1) * 0.5f);
                float a = sa * sa + cosf(la1) * cosf(la2) * sb * sb;
                a = fminf(fmaxf(a, 0.f), 1.f);
                float cc = 2.f * atan2f(sqrtf(a), sqrtf(fmaxf(1.f - a, 1e-12f)));
                f3 = log1pf(6371.0088f * cc);
            }
            xs[warp * DIN + 256] = s;  xs[warp * DIN + 257] = c;
            xs[warp * DIN + 258] = f2; xs[warp * DIN + 259] = f3;
        }
        __syncwarp();
        float sm = 0.f, s2 = 0.f;
        for (int k = lane; k < DIN; k += 32) { float v = xs[warp * DIN + k]; sm += v; s2 += v * v; }
        sm = warp_sum(sm); s2 = warp_sum(s2);
        const float mu = sm * (1.f / DIN);
        const float inv = rsqrtf(s2 * (1.f / DIN) - mu * mu + 1e-5f);
        for (int k = lane; k < DIN; k += 32) {
            float v = xs[warp * DIN + k];
            xs[warp * DIN + k] = (v - mu) * inv * __ldg(&lnw[k]) + __ldg(&lnb[k]);
        }
    }
    __syncthreads();

    // hidden = GELU(x @ W1 + b1); thread owns h0=tid and h1=tid+256
    float acc0[8], acc1[8];
#pragma unroll
    for (int i = 0; i < 8; i++) { acc0[i] = 0.f; acc1[i] = 0.f; }
    const int h0 = tid, h1 = tid + 256;
    const bool h1v = (h1 < DHID);
    for (int k4 = 0; k4 < DIN / 4; k4++) {
        float4 xv[8];
#pragma unroll
        for (int i = 0; i < 8; i++) xv[i] = *(const float4*)(xs + i * DIN + 4 * k4);
#pragma unroll
        for (int c = 0; c < 4; c++) {
            const int k = 4 * k4 + c;
            const float wa = __ldg(&w1[k * DHID + h0]);
            const float wb = h1v ? __ldg(&w1[k * DHID + h1]) : 0.f;
#pragma unroll
            for (int i = 0; i < 8; i++) {
                float xk = (c == 0) ? xv[i].x : (c == 1) ? xv[i].y : (c == 2) ? xv[i].z : xv[i].w;
                acc0[i] = fmaf(xk, wa, acc0[i]);
                acc1[i] = fmaf(xk, wb, acc1[i]);
            }
        }
    }
    {
        const float bb0 = __ldg(&b1[h0]);
        const float bb1 = h1v ? __ldg(&b1[h1]) : 0.f;
#pragma unroll
        for (int i = 0; i < 8; i++) {
            float v = acc0[i] + bb0;
            hb[i * DHID + h0] = 0.5f * v * (1.f + erff(v * 0.7071067811865475f));
            if (h1v) {
                float u = acc1[i] + bb1;
                hb[i * DHID + h1] = 0.5f * u * (1.f + erff(u * 0.7071067811865475f));
            }
        }
    }
    __syncthreads();

    // out = hidden @ W2 + b2; thread owns o=tid
    float acc[8];
#pragma unroll
    for (int i = 0; i < 8; i++) acc[i] = 0.f;
    for (int k4 = 0; k4 < DHID / 4; k4++) {
        float4 hv[8];
#pragma unroll
        for (int i = 0; i < 8; i++) hv[i] = *(const float4*)(hb + i * DHID + 4 * k4);
#pragma unroll
        for (int c = 0; c < 4; c++) {
            const int k = 4 * k4 + c;
            const float w = __ldg(&w2[k * DPOI + tid]);
#pragma unroll
            for (int i = 0; i < 8; i++) {
                float xk = (c == 0) ? hv[i].x : (c == 1) ? hv[i].y : (c == 2) ? hv[i].z : hv[i].w;
                acc[i] = fmaf(xk, w, acc[i]);
            }
        }
    }
    const float bo = __ldg(&b2[tid]);
#pragma unroll
    for (int i = 0; i < 8; i++) g_x[(t0 + i) * DPOI + tid] = acc[i] + bo;
}

// ---------------------------------------------------------------- K2: gi = x @ W_ih^T + b_ih
__global__ __launch_bounds__(256) void k2_gi(
    const float* __restrict__ wih, const float* __restrict__ bih)
{
    __shared__ float xsm[8 * DPOI];
    __shared__ float wsmT[16 * 257];
    const int tid = threadIdx.x;
    const int t0 = blockIdx.x * 8;
    const int g0 = blockIdx.y * 256;

    for (int i = tid; i < 8 * DPOI; i += 256) xsm[i] = g_x[t0 * DPOI + i];

    float acc[8];
#pragma unroll
    for (int i = 0; i < 8; i++) acc[i] = 0.f;

    for (int k0 = 0; k0 < DPOI; k0 += 16) {
        __syncthreads();
        for (int i = tid; i < 4096; i += 256) {
            const int kk = i & 15, g = i >> 4;
            wsmT[kk * 257 + g] = wih[(size_t)(g0 + g) * DPOI + k0 + kk];
        }
        __syncthreads();
#pragma unroll
        for (int k4 = 0; k4 < 4; k4++) {
            float4 xv[8];
#pragma unroll
            for (int i = 0; i < 8; i++) xv[i] = *(const float4*)(xsm + i * DPOI + k0 + 4 * k4);
#pragma unroll
            for (int c = 0; c < 4; c++) {
                const float w = wsmT[(4 * k4 + c) * 257 + tid];
#pragma unroll
                for (int i = 0; i < 8; i++) {
                    float xk = (c == 0) ? xv[i].x : (c == 1) ? xv[i].y : (c == 2) ? xv[i].z : xv[i].w;
                    acc[i] = fmaf(xk, w, acc[i]);
                }
            }
        }
    }
    const float b = __ldg(&bih[g0 + tid]);
#pragma unroll
    for (int i = 0; i < 8; i++) g_gi[(size_t)(t0 + i) * G3 + g0 + tid] = acc[i] + b;
}

// ---------------------------------------------------------------- K3: GRU scan, 16-CTA cluster
// CTA c owns h-dims [32c, 32c+32). W_hh slice (96 rows x 512) lives in REGISTERS:
// warp w holds rows lr = 6w..6w+5 (lr -> gate lr>>5, dim lr&31); lane l holds
// column pairs (2p, 2p+1) for p = l + 32j, j=0..7, packed as f32x2.
__global__ void __launch_bounds__(512, 1) __cluster_dims__(CL, 1, 1)
k3_gru(const float* __restrict__ whh, const float* __restrict__ bhh)
{
    __shared__ float hbuf[2][HH];
    __shared__ float ghs[RPC];
    __shared__ float gis[RPC];
    __shared__ float bsh[RPC];

    const int tid = threadIdx.x, warp = tid >> 5, lane = tid & 31;
    unsigned c;
    asm("mov.u32 %0, %%cluster_ctarank;" : "=r"(c));

    // load resident weight registers (48 f32x2 per thread)
    unsigned long long w[RPW][8];
#pragma unroll
    for (int r = 0; r < RPW; r++) {
        const int lr = warp * RPW + r;
        const int grow = (lr >> 5) * HH + c * DPC + (lr & 31);
        const unsigned long long* wp = (const unsigned long long*)(whh + (size_t)grow * HH);
#pragma unroll
        for (int j = 0; j < 8; j++) w[r][j] = wp[lane + 32 * j];
    }
    if (tid < RPC) {
        const int grow = (tid >> 5) * HH + c * DPC + (tid & 31);
        bsh[tid] = bhh[grow];
    }
    hbuf[0][tid] = 0.f;
    __syncthreads();
    cluster_sync_();   // peers' smem initialized before any DSMEM writes land

    const int my_grow = (tid < RPC) ? ((tid >> 5) * HH + c * DPC + (tid & 31)) : 0;
    const unsigned hb_base = smem_u32(&hbuf[0][0]);

    for (int t = 0; t < TT; t++) {
        const int cur = t & 1, nxt = cur ^ 1;

        float gval = 0.f;
        if (tid < RPC) gval = __ldcg(&g_gi[(size_t)t * G3 + my_grow]);

        // 96 dot products per CTA, f32x2 FMA
        unsigned long long acc[RPW];
#pragma unroll
        for (int r = 0; r < RPW; r++) acc[r] = 0ull;
        const unsigned long long* h2 = (const unsigned long long*)hbuf[cur];
#pragma unroll
        for (int j = 0; j < 8; j++) {
            const unsigned long long hv = h2[lane + 32 * j];
#pragma unroll
            for (int r = 0; r < RPW; r++)
                asm("fma.rn.f32x2 %0, %1, %2, %0;" : "+l"(acc[r]) : "l"(w[r][j]), "l"(hv));
        }
#pragma unroll
        for (int r = 0; r < RPW; r++) {
            float lo, hi;
            asm("mov.b64 {%0, %1}, %2;" : "=f"(lo), "=f"(hi) : "l"(acc[r]));
            float s = warp_sum(lo + hi);
            if (lane == 0) ghs[warp * RPW + r] = s;
        }
        if (tid < RPC) gis[tid] = gval;
        __syncthreads();

        if (tid < DPC) {
            const int m = tid;
            const float r = 1.f / (1.f + expf(-(gis[m]      + ghs[m]      + bsh[m])));
            const float z = 1.f / (1.f + expf(-(gis[32 + m] + ghs[32 + m] + bsh[32 + m])));
            const float n = tanhf(gis[64 + m] + r * (ghs[64 + m] + bsh[64 + m]));
            const float hn = (1.f - z) * n + z * hbuf[cur][c * DPC + m];
            g_hs[(size_t)t * HH + c * DPC + m] = hn;
            const unsigned dst = hb_base + (unsigned)((nxt * HH + c * DPC + m) * 4);
#pragma unroll
            for (unsigned rk = 0; rk < CL; rk++) st_dsmem(dst, rk, hn);
        }
        cluster_sync_();
    }
}

// ---------------------------------------------------------------- K4: score + softmax + summary
__global__ __launch_bounds__(512) void k4_epi(
    const float* __restrict__ q, const float* __restrict__ loglam,
    float* __restrict__ out, int out_size)
{
    __shared__ float qs[HH];
    __shared__ float sc[TT];
    __shared__ float red[16];
    const int tid = threadIdx.x, warp = tid >> 5, lane = tid & 31;
    const float lam = fmaxf(expf(loglam[0]), 1e-4f);

    qs[tid] = q[tid] * rsqrtf((float)HH);
    __syncthreads();

    for (int rr = 0; rr < 32; rr++) {
        const int t = warp * 32 + rr;
        float a = 0.f;
#pragma unroll
        for (int i = 0; i < 16; i++)
            a = fmaf(g_hs[(size_t)t * HH + lane + 32 * i], qs[lane + 32 * i], a);
        a = warp_sum(a);
        if (lane == 0) sc[t] = a - lam * (float)(TT - 1 - t);
    }
    __syncthreads();

    float v = sc[tid];
    float m = v;
#pragma unroll
    for (int o = 16; o > 0; o >>= 1) m = fmaxf(m, __shfl_xor_sync(0xffffffffu, m, o));
    if (lane == 0) red[warp] = m;
    __syncthreads();
    if (tid < 16) {
        float x = red[tid];
#pragma unroll
        for (int o = 8; o > 0; o >>= 1) x = fmaxf(x, __shfl_xor_sync(0xffffu, x, o));
        if (tid == 0) red[0] = x;
    }
    __syncthreads();
    const float mx = red[0];
    float e = expf(v - mx);
    float s = warp_sum(e);
    __syncthreads();
    if (lane == 0) red[warp] = s;
    __syncthreads();
    if (tid < 16) {
        float x = red[tid];
#pragma unroll
        for (int o = 8; o > 0; o >>= 1) x += __shfl_xor_sync(0xffffu, x, o);
        if (tid == 0) red[0] = x;
    }
    __syncthreads();
    const float attn = e / red[0];
    sc[tid] = attn;
    if (out_size >= 1024) out[HH + tid] = attn;
    __syncthreads();

    float acc = 0.f;
    for (int t = 0; t < TT; t += 4) {
        acc = fmaf(sc[t],     g_hs[(size_t)t       * HH + tid], acc);
        acc = fmaf(sc[t + 1], g_hs[(size_t)(t + 1) * HH + tid], acc);
        acc = fmaf(sc[t + 2], g_hs[(size_t)(t + 2) * HH + tid], acc);
        acc = fmaf(sc[t + 3], g_hs[(size_t)(t + 3) * HH + tid], acc);
    }
    if (tid < out_size) out[tid] = acc;
}

// ---------------------------------------------------------------- launch
extern "C" void kernel_launch(void* const* d_in, const int* in_sizes, int n_in,
                              void* d_out, int out_size) {
    const int*   idx = (const int*)  d_in[0];
    const float* tf  = (const float*)d_in[1];
    const float* emb = (const float*)d_in[2];
    const float* ll  = (const float*)d_in[3];
    const float* lnw = (const float*)d_in[4];
    const float* lnb = (const float*)d_in[5];
    const float* w1  = (const float*)d_in[6];
    const float* b1  = (const float*)d_in[7];
    const float* w2  = (const float*)d_in[8];
    const float* b2  = (const float*)d_in[9];
    const float* wih = (const float*)d_in[10];
    const float* whh = (const float*)d_in[11];
    const float* bih = (const float*)d_in[12];
    const float* bhh = (const float*)d_in[13];
    const float* q   = (const float*)d_in[14];
    const float* llm = (const float*)d_in[15];
    float* out = (float*)d_out;

    static int attr_done = 0;
    if (!attr_done) {
        cudaFuncSetAttribute(k3_gru, cudaFuncAttributeNonPortableClusterSizeAllowed, 1);
        attr_done = 1;
    }

    k1_feat_mlp<<<64, 256>>>(idx, tf, emb, ll, lnw, lnb, w1, b1, w2, b2);
    k2_gi<<<dim3(64, 6), 256>>>(wih, bih);
    k3_gru<<<CL, 512>>>(whh, bhh);
    k4_epi<<<1, 512>>>(q, llm, out, out_size);
}

// round 5
// speedup vs baseline: 3.4394x; 1.2240x over previous
#include <cuda_runtime.h>
#include <math.h>

#define TT    512
#define DPOI  256
#define DIN   260
#define DHID  356
#define G3    1536
#define HH    512
#define CL    16          // cluster size
#define DPC   32          // h-dims per CTA
#define RPC   96          // rows per CTA (3 gates * 32)
#define RPW   6           // rows per warp

__device__ float g_x [TT * DPOI];
__device__ float g_gi[TT * G3];

__device__ __forceinline__ float warp_sum(float v) {
#pragma unroll
    for (int o = 16; o > 0; o >>= 1) v += __shfl_xor_sync(0xffffffffu, v, o);
    return v;
}
__device__ __forceinline__ unsigned smem_u32(const void* p) {
    unsigned a;
    asm("{ .reg .u64 t; cvta.to.shared.u64 t, %1; cvt.u32.u64 %0, t; }" : "=r"(a) : "l"(p));
    return a;
}
__device__ __forceinline__ void st_dsmem(unsigned addr, unsigned rank, float v) {
    unsigned ra;
    asm volatile("mapa.shared::cluster.u32 %0, %1, %2;" : "=r"(ra) : "r"(addr), "r"(rank));
    asm volatile("st.shared::cluster.f32 [%0], %1;" :: "r"(ra), "f"(v) : "memory");
}
__device__ __forceinline__ void cluster_sync_() {
    asm volatile("barrier.cluster.arrive.aligned;" ::: "memory");
    asm volatile("barrier.cluster.wait.aligned;"   ::: "memory");
}
__device__ __forceinline__ void mbar_init(unsigned a, unsigned cnt) {
    asm volatile("mbarrier.init.shared.b64 [%0], %1;" :: "r"(a), "r"(cnt) : "memory");
}
__device__ __forceinline__ void mbar_expect(unsigned a, unsigned tx) {
    asm volatile("mbarrier.arrive.expect_tx.shared.b64 _, [%0], %1;" :: "r"(a), "r"(tx) : "memory");
}
__device__ __forceinline__ void mbar_arrive_remote(unsigned a, unsigned rk) {
    unsigned ra;
    asm volatile("mapa.shared::cluster.u32 %0, %1, %2;" : "=r"(ra) : "r"(a), "r"(rk));
    asm volatile("mbarrier.arrive.shared::cluster.b64 _, [%0];" :: "r"(ra) : "memory");
}
__device__ __forceinline__ void mbar_wait(unsigned a, unsigned parity) {
    unsigned done;
    asm volatile(
        "{\n\t.reg .pred p;\n\t"
        "mbarrier.try_wait.parity.acquire.cta.shared::cta.b64 p, [%1], %2;\n\t"
        "selp.b32 %0, 1, 0, p;\n\t}"
        : "=r"(done) : "r"(a), "r"(parity) : "memory");
    if (!done) {
        asm volatile(
            "{\n\t.reg .pred P1;\n\t"
            "W_%=:\n\t"
            "mbarrier.try_wait.parity.acquire.cta.shared::cta.b64 P1, [%0], %1;\n\t"
            "@P1 bra.uni D_%=;\n\t"
            "bra.uni W_%=;\n\t"
            "D_%=:\n\t}"
            :: "r"(a), "r"(parity) : "memory");
    }
}
__device__ __forceinline__ void st_async_f32(unsigned dst, unsigned bar, unsigned rk, float v) {
    unsigned rd, rb;
    asm volatile("mapa.shared::cluster.u32 %0, %1, %2;" : "=r"(rd) : "r"(dst), "r"(rk));
    asm volatile("mapa.shared::cluster.u32 %0, %1, %2;" : "=r"(rb) : "r"(bar), "r"(rk));
    asm volatile("st.async.shared::cluster.mbarrier::complete_tx::bytes.b32 [%0], %1, [%2];"
                 :: "r"(rd), "r"(__float_as_uint(v)), "r"(rb) : "memory");
}

// ---------------------------------------------------------------- K1: gather+feat+LN+MLP
__global__ __launch_bounds__(256) void k1_feat_mlp(
    const int* __restrict__ idx, const float* __restrict__ tf,
    const float* __restrict__ emb, const float* __restrict__ ll,
    const float* __restrict__ lnw, const float* __restrict__ lnb,
    const float* __restrict__ w1, const float* __restrict__ b1,
    const float* __restrict__ w2, const float* __restrict__ b2)
{
    __shared__ float xs[8 * DIN];
    __shared__ float hb[8 * DHID];
    const int tid = threadIdx.x, warp = tid >> 5, lane = tid & 31;
    const int t0 = blockIdx.x * 8;

    {   // one warp per timestep: gather + features + LayerNorm
        const int t = t0 + warp;
        const int pid = idx[t];
        const float4* er = (const float4*)(emb + (size_t)pid * DPOI);
        *(float4*)(xs + warp * DIN + 4 * lane)       = er[lane];
        *(float4*)(xs + warp * DIN + 128 + 4 * lane) = er[lane + 32];
        if (lane == 0) {
            float tc = fminf(fmaxf(tf[t], 0.f), 1.f);
            float s, c; sincosf(6.283185307179586f * tc, &s, &c);
            float f2 = 0.f, f3 = 0.f;
            if (t > 0) {
                float tp = fminf(fmaxf(tf[t - 1], 0.f), 1.f);
                float d = tc - tp;
                float m = d - floorf(d);
                f2 = log1pf(m * 24.f);
                const int ia = idx[t - 1];
                const float R = 0.017453292519943295f;
                float la1 = R * fminf(fmaxf(ll[2 * ia  + 0],  -90.f),  90.f);
                float lo1 = R * fminf(fmaxf(ll[2 * ia  + 1], -180.f), 180.f);
                float la2 = R * fminf(fmaxf(ll[2 * pid + 0],  -90.f),  90.f);
                float lo2 = R * fminf(fmaxf(ll[2 * pid + 1], -180.f), 180.f);
                float sa = sinf((la2 - la1) * 0.5f);
                float sb = sinf((lo2 - lo1) * 0.5f);
                float a = sa * sa + cosf(la1) * cosf(la2) * sb * sb;
                a = fminf(fmaxf(a, 0.f), 1.f);
                float cc = 2.f * atan2f(sqrtf(a), sqrtf(fmaxf(1.f - a, 1e-12f)));
                f3 = log1pf(6371.0088f * cc);
            }
            xs[warp * DIN + 256] = s;  xs[warp * DIN + 257] = c;
            xs[warp * DIN + 258] = f2; xs[warp * DIN + 259] = f3;
        }
        __syncwarp();
        float sm = 0.f, s2 = 0.f;
        for (int k = lane; k < DIN; k += 32) { float v = xs[warp * DIN + k]; sm += v; s2 += v * v; }
        sm = warp_sum(sm); s2 = warp_sum(s2);
        const float mu = sm * (1.f / DIN);
        const float inv = rsqrtf(s2 * (1.f / DIN) - mu * mu + 1e-5f);
        for (int k = lane; k < DIN; k += 32) {
            float v = xs[warp * DIN + k];
            xs[warp * DIN + k] = (v - mu) * inv * __ldg(&lnw[k]) + __ldg(&lnb[k]);
        }
    }
    __syncthreads();

    float acc0[8], acc1[8];
#pragma unroll
    for (int i = 0; i < 8; i++) { acc0[i] = 0.f; acc1[i] = 0.f; }
    const int h0 = tid, h1 = tid + 256;
    const bool h1v = (h1 < DHID);
    for (int k4 = 0; k4 < DIN / 4; k4++) {
        float4 xv[8];
#pragma unroll
        for (int i = 0; i < 8; i++) xv[i] = *(const float4*)(xs + i * DIN + 4 * k4);
#pragma unroll
        for (int c = 0; c < 4; c++) {
            const int k = 4 * k4 + c;
            const float wa = __ldg(&w1[k * DHID + h0]);
            const float wb = h1v ? __ldg(&w1[k * DHID + h1]) : 0.f;
#pragma unroll
            for (int i = 0; i < 8; i++) {
                float xk = (c == 0) ? xv[i].x : (c == 1) ? xv[i].y : (c == 2) ? xv[i].z : xv[i].w;
                acc0[i] = fmaf(xk, wa, acc0[i]);
                acc1[i] = fmaf(xk, wb, acc1[i]);
            }
        }
    }
    {
        const float bb0 = __ldg(&b1[h0]);
        const float bb1 = h1v ? __ldg(&b1[h1]) : 0.f;
#pragma unroll
        for (int i = 0; i < 8; i++) {
            float v = acc0[i] + bb0;
            hb[i * DHID + h0] = 0.5f * v * (1.f + erff(v * 0.7071067811865475f));
            if (h1v) {
                float u = acc1[i] + bb1;
                hb[i * DHID + h1] = 0.5f * u * (1.f + erff(u * 0.7071067811865475f));
            }
        }
    }
    __syncthreads();

    float acc[8];
#pragma unroll
    for (int i = 0; i < 8; i++) acc[i] = 0.f;
    for (int k4 = 0; k4 < DHID / 4; k4++) {
        float4 hv[8];
#pragma unroll
        for (int i = 0; i < 8; i++) hv[i] = *(const float4*)(hb + i * DHID + 4 * k4);
#pragma unroll
        for (int c = 0; c < 4; c++) {
            const int k = 4 * k4 + c;
            const float w = __ldg(&w2[k * DPOI + tid]);
#pragma unroll
            for (int i = 0; i < 8; i++) {
                float xk = (c == 0) ? hv[i].x : (c == 1) ? hv[i].y : (c == 2) ? hv[i].z : hv[i].w;
                acc[i] = fmaf(xk, w, acc[i]);
            }
        }
    }
    const float bo = __ldg(&b2[tid]);
#pragma unroll
    for (int i = 0; i < 8; i++) g_x[(t0 + i) * DPOI + tid] = acc[i] + bo;
}

// ---------------------------------------------------------------- K2: gi = x @ W_ih^T + b_ih
__global__ __launch_bounds__(256) void k2_gi(
    const float* __restrict__ wih, const float* __restrict__ bih)
{
    __shared__ float xsm[8 * DPOI];
    __shared__ float wsmT[16 * 257];
    const int tid = threadIdx.x;
    const int t0 = blockIdx.x * 8;
    const int g0 = blockIdx.y * 256;

    for (int i = tid; i < 8 * DPOI; i += 256) xsm[i] = g_x[t0 * DPOI + i];

    float acc[8];
#pragma unroll
    for (int i = 0; i < 8; i++) acc[i] = 0.f;

    for (int k0 = 0; k0 < DPOI; k0 += 16) {
        __syncthreads();
        for (int i = tid; i < 4096; i += 256) {
            const int kk = i & 15, g = i >> 4;
            wsmT[kk * 257 + g] = wih[(size_t)(g0 + g) * DPOI + k0 + kk];
        }
        __syncthreads();
#pragma unroll
        for (int k4 = 0; k4 < 4; k4++) {
            float4 xv[8];
#pragma unroll
            for (int i = 0; i < 8; i++) xv[i] = *(const float4*)(xsm + i * DPOI + k0 + 4 * k4);
#pragma unroll
            for (int c = 0; c < 4; c++) {
                const float w = wsmT[(4 * k4 + c) * 257 + tid];
#pragma unroll
                for (int i = 0; i < 8; i++) {
                    float xk = (c == 0) ? xv[i].x : (c == 1) ? xv[i].y : (c == 2) ? xv[i].z : xv[i].w;
                    acc[i] = fmaf(xk, w, acc[i]);
                }
            }
        }
    }
    const float b = __ldg(&bih[g0 + tid]);
#pragma unroll
    for (int i = 0; i < 8; i++) g_gi[(size_t)(t0 + i) * G3 + g0 + tid] = acc[i] + b;
}

// ---------------------------------------------------------------- K3: GRU scan + fused epilogue
// 16-CTA cluster, mbarrier dataflow pipeline over a 4-slot h ring.
// CTA c owns h-dims [32c,32c+32); W_hh slice (96x512) in registers as f32x2.
__global__ void __launch_bounds__(512, 1) __cluster_dims__(CL, 1, 1)
k3_gru(const float* __restrict__ whh, const float* __restrict__ bhh,
       const float* __restrict__ gq, const float* __restrict__ loglam,
       float* __restrict__ out, int out_size)
{
    extern __shared__ float sm[];
    float* hbuf = sm;                    // 4 * 512
    float* hist = sm + 2048;             // 512 * 32
    float* part = sm + 18432;            // 16 * 512
    float* scp  = sm + 26624;            // 512
    float* attn = sm + 27136;            // 512
    float* ghs  = sm + 27648;            // 96
    float* gis  = sm + 27744;            // 96
    float* bsh  = sm + 27840;            // 96
    float* qv   = sm + 27936;            // 32
    float* red  = sm + 27968;            // 16
    const unsigned mb = smem_u32(sm + 27984);   // full[4] @ +0, empty[4] @ +32
#define MB_FULL(s)  (mb + (unsigned)((s) * 8))
#define MB_EMPTY(s) (mb + 32u + (unsigned)((s) * 8))

    const int tid = threadIdx.x, warp = tid >> 5, lane = tid & 31;
    unsigned c; asm("mov.u32 %0, %%cluster_ctarank;" : "=r"(c));

    if (tid == 0) {
#pragma unroll
        for (int s = 0; s < 4; s++) { mbar_init(MB_FULL(s), 1); mbar_init(MB_EMPTY(s), CL); }
    }
    for (int i = tid; i < 2048; i += 512) hbuf[i] = 0.f;
    if (tid < RPC) bsh[tid] = bhh[(tid >> 5) * HH + (int)c * DPC + (tid & 31)];
    if (tid < 32)  qv[tid]  = gq[(int)c * DPC + tid] * rsqrtf((float)HH);

    // resident weight registers: warp w rows 6w..6w+5; lane l col-pairs l+32j
    unsigned long long w[RPW][8];
#pragma unroll
    for (int r = 0; r < RPW; r++) {
        const int lr = warp * RPW + r;
        const int grow = (lr >> 5) * HH + (int)c * DPC + (lr & 31);
        const unsigned long long* wp = (const unsigned long long*)(whh + (size_t)grow * HH);
#pragma unroll
        for (int j = 0; j < 8; j++) w[r][j] = wp[lane + 32 * j];
    }
    __syncthreads();
    cluster_sync_();   // mbarriers + zeros visible everywhere before traffic

    const unsigned hb_base = smem_u32(hbuf);
    const int my_grow = (tid < RPC) ? ((tid >> 5) * HH + (int)c * DPC + (tid & 31)) : 0;

    for (int t = 0; t < TT; t++) {
        const int wsl = t & 3, psl = (t + 3) & 3;
        if (t > 0) mbar_wait(MB_FULL(psl), ((unsigned)(t - 1) >> 2) & 1u);
        if (tid == 0) mbar_expect(MB_FULL(wsl), 2048u);

        float gval = 0.f;
        if (tid < RPC) gval = __ldcg(&g_gi[(size_t)t * G3 + my_grow]);
        const float h_own = (tid < 32) ? hbuf[psl * 512 + (int)c * DPC + tid] : 0.f;

        const unsigned long long* h2 = (const unsigned long long*)(hbuf + psl * 512);
        unsigned long long acc[RPW];
#pragma unroll
        for (int r = 0; r < RPW; r++) acc[r] = 0ull;
#pragma unroll
        for (int j = 0; j < 8; j++) {
            const unsigned long long hv = h2[lane + 32 * j];
#pragma unroll
            for (int r = 0; r < RPW; r++)
                asm("fma.rn.f32x2 %0, %1, %2, %0;" : "+l"(acc[r]) : "l"(w[r][j]), "l"(hv));
        }
#pragma unroll
        for (int r = 0; r < RPW; r++) {
            float lo, hi;
            asm("mov.b64 {%0, %1}, %2;" : "=f"(lo), "=f"(hi) : "l"(acc[r]));
            const float s = warp_sum(lo + hi);
            if (lane == 0) ghs[warp * RPW + r] = s;
        }
        if (tid < RPC) gis[tid] = gval;
        __syncthreads();

        // slot psl fully read by this CTA -> free it on every rank
        if (t > 0 && tid >= 32 && tid < 48) mbar_arrive_remote(MB_EMPTY(psl), (unsigned)(tid - 32));

        if (tid < 32) {
            if (t >= 4) mbar_wait(MB_EMPTY(wsl), (((unsigned)t >> 2) - 1u) & 1u);
            const int m = tid;
            const float rg = 1.f / (1.f + expf(-(gis[m]      + ghs[m]      + bsh[m])));
            const float zg = 1.f / (1.f + expf(-(gis[32 + m] + ghs[32 + m] + bsh[32 + m])));
            const float ng = tanhf(gis[64 + m] + rg * (ghs[64 + m] + bsh[64 + m]));
            const float hn = (1.f - zg) * ng + zg * h_own;
            hist[t * 32 + m] = hn;
            const unsigned dst = hb_base + (unsigned)((wsl * 512 + (int)c * DPC + m) * 4);
            const unsigned bar = MB_FULL(wsl);
#pragma unroll
            for (unsigned rk = 0; rk < CL; rk++) st_async_f32(dst, bar, rk, hn);
        }
    }
    __syncthreads();

    // ---- fused epilogue ----
    // partial scores for this CTA's 32 dims
    {
        float a = 0.f;
#pragma unroll
        for (int m = 0; m < 32; m += 4) {
            const float4 hv4 = *(const float4*)(hist + tid * 32 + m);
            a = fmaf(hv4.x, qv[m],     a);
            a = fmaf(hv4.y, qv[m + 1], a);
            a = fmaf(hv4.z, qv[m + 2], a);
            a = fmaf(hv4.w, qv[m + 3], a);
        }
        scp[tid] = a;
    }
    __syncthreads();
    {   // ship partials to rank 0
        const unsigned paddr = smem_u32(part) + (unsigned)(((int)c * 512 + tid) * 4);
        st_dsmem(paddr, 0u, scp[tid]);
    }
    cluster_sync_();

    if (c == 0) {   // softmax on rank 0, broadcast attn
        const float lam = fmaxf(expf(loglam[0]), 1e-4f);
        float s = 0.f;
#pragma unroll
        for (int cc = 0; cc < CL; cc++) s += part[cc * 512 + tid];
        s -= lam * (float)(TT - 1 - tid);

        float m = s;
#pragma unroll
        for (int o = 16; o > 0; o >>= 1) m = fmaxf(m, __shfl_xor_sync(0xffffffffu, m, o));
        if (lane == 0) red[warp] = m;
        __syncthreads();
        if (tid < 16) {
            float x = red[tid];
#pragma unroll
            for (int o = 8; o > 0; o >>= 1) x = fmaxf(x, __shfl_xor_sync(0xffffu, x, o));
            if (tid == 0) red[0] = x;
        }
        __syncthreads();
        const float mx = red[0];
        const float e = expf(s - mx);
        float ssum = warp_sum(e);
        __syncthreads();
        if (lane == 0) red[warp] = ssum;
        __syncthreads();
        if (tid < 16) {
            float x = red[tid];
#pragma unroll
            for (int o = 8; o > 0; o >>= 1) x += __shfl_xor_sync(0xffffu, x, o);
            if (tid == 0) red[0] = x;
        }
        __syncthreads();
        const float a = e / red[0];
        attn[tid] = a;
        if (out_size >= 1024) out[HH + tid] = a;
        const unsigned aaddr = smem_u32(attn) + (unsigned)(tid * 4);
        for (unsigned rk = 1; rk < CL; rk++) st_dsmem(aaddr, rk, a);
    }
    cluster_sync_();

    // summary for this CTA's 32 dims: thread (g,d) sums 32 timesteps
    {
        const int d = tid & 31, g = tid >> 5;
        float a = 0.f;
#pragma unroll 4
        for (int i = 0; i < 32; i++) {
            const int t = g * 32 + i;
            a = fmaf(attn[t], hist[t * 32 + d], a);
        }
        scp[g * 32 + d] = a;
    }
    __syncthreads();
    if (tid < 32) {
        float s = 0.f;
#pragma unroll
        for (int g = 0; g < 16; g++) s += scp[g * 32 + tid];
        const int o = (int)c * DPC + tid;
        if (o < out_size) out[o] = s;
    }
    cluster_sync_();   // no CTA exits with peer traffic in flight
}

// ---------------------------------------------------------------- launch
extern "C" void kernel_launch(void* const* d_in, const int* in_sizes, int n_in,
                              void* d_out, int out_size) {
    const int*   idx = (const int*)  d_in[0];
    const float* tf  = (const float*)d_in[1];
    const float* emb = (const float*)d_in[2];
    const float* ll  = (const float*)d_in[3];
    const float* lnw = (const float*)d_in[4];
    const float* lnb = (const float*)d_in[5];
    const float* w1  = (const float*)d_in[6];
    const float* b1  = (const float*)d_in[7];
    const float* w2  = (const float*)d_in[8];
    const float* b2  = (const float*)d_in[9];
    const float* wih = (const float*)d_in[10];
    const float* whh = (const float*)d_in[11];
    const float* bih = (const float*)d_in[12];
    const float* bhh = (const float*)d_in[13];
    const float* q   = (const float*)d_in[14];
    const float* llm = (const float*)d_in[15];
    float* out = (float*)d_out;

    const int k3_smem = 28000 * (int)sizeof(float);   // 112000 B dynamic

    static int attr_done = 0;
    if (!attr_done) {
        cudaFuncSetAttribute(k3_gru, cudaFuncAttributeNonPortableClusterSizeAllowed, 1);
        cudaFuncSetAttribute(k3_gru, cudaFuncAttributeMaxDynamicSharedMemorySize, k3_smem);
        attr_done = 1;
    }

    k1_feat_mlp<<<64, 256>>>(idx, tf, emb, ll, lnw, lnb, w1, b1, w2, b2);
    k2_gi<<<dim3(64, 6), 256>>>(wih, bih);
    k3_gru<<<CL, 512, k3_smem>>>(whh, bhh, q, llm, out, out_size);
}